// round 1
// baseline (speedup 1.0000x reference)
#include <cuda_runtime.h>
#include <cstdint>
#include <cstdio>

// Problem constants
static constexpr int CB = 4;        // batch
static constexpr int CT = 1024;     // seq len
static constexpr int CD = 1024;     // d_model
static constexpr int CH = 16;       // heads
static constexpr int CHS = 64;      // head size
static constexpr int CL = 4;        // layers
static constexpr int CFF = 4096;    // ffn dim
static constexpr int CV = 32000;    // vocab
static constexpr int CM = CB * CT;  // 4096 rows

// ---------------- scratch (device globals; no allocation allowed) ----------
__device__ float g_x[CM * CD];          // residual stream (16 MB)
__device__ float g_h[CM * CD];          // ln output / attn-out (16 MB)
__device__ float g_qkv[CM * 3 * CD];    // packed qkv activations (50 MB)
__device__ float g_act[CM * CFF];       // ffn activation (67 MB)
__device__ float g_wpack[CL * CD * 3 * CD]; // packed qkv weights (50 MB)

// ---------------- embedding -----------------------------------------------
__global__ void embed_kernel(const int* __restrict__ ids,
                             const float* __restrict__ tok_emb,
                             const float* __restrict__ pos_emb,
                             float* __restrict__ x) {
    int idx = blockIdx.x * blockDim.x + threadIdx.x;
    if (idx >= CM * CD) return;
    int d = idx % CD;
    int bt = idx / CD;
    int t = bt % CT;
    x[idx] = tok_emb[(size_t)ids[bt] * CD + d] + pos_emb[t * CD + d];
}

// ---------------- qkv weight pack: (L,H,D,HS)x3 -> (L, D, 3*H*HS) ----------
__global__ void pack_qkv_kernel(const float* __restrict__ wq,
                                const float* __restrict__ wk,
                                const float* __restrict__ wv,
                                float* __restrict__ wp) {
    const int PER = CL * CH * CD * CHS; // 4194304
    int idx = blockIdx.x * blockDim.x + threadIdx.x;
    if (idx >= 3 * PER) return;
    int which = idx / PER;
    int r = idx % PER;
    int e = r % CHS;
    int d = (r / CHS) % CD;
    int h = (r / (CHS * CD)) % CH;
    int l = r / (CHS * CD * CH);
    const float* src = (which == 0) ? wq : (which == 1) ? wk : wv;
    wp[((size_t)l * CD + d) * (3 * CD) + which * CD + h * CHS + e] = src[r];
}

// ---------------- layernorm ------------------------------------------------
__device__ __forceinline__ float warp_sum(float v) {
    #pragma unroll
    for (int o = 16; o; o >>= 1) v += __shfl_xor_sync(0xffffffffu, v, o);
    return v;
}

__global__ void ln_kernel(const float* __restrict__ x,
                          const float* __restrict__ g,
                          const float* __restrict__ b,
                          float* __restrict__ out) {
    int row = blockIdx.x;
    int tid = threadIdx.x; // 256, each handles 4 elems
    const float4* xr = (const float4*)(x + (size_t)row * CD);
    float4 v = xr[tid];
    float s = v.x + v.y + v.z + v.w;
    float s2 = v.x * v.x + v.y * v.y + v.z * v.z + v.w * v.w;
    s = warp_sum(s);
    s2 = warp_sum(s2);
    __shared__ float shs[8], shs2[8];
    int w = tid >> 5, lane = tid & 31;
    if (lane == 0) { shs[w] = s; shs2[w] = s2; }
    __syncthreads();
    if (tid == 0) {
        float a = 0.f, a2 = 0.f;
        #pragma unroll
        for (int i = 0; i < 8; i++) { a += shs[i]; a2 += shs2[i]; }
        shs[0] = a; shs2[0] = a2;
    }
    __syncthreads();
    float mean = shs[0] * (1.f / CD);
    float var = shs2[0] * (1.f / CD) - mean * mean;
    float rstd = rsqrtf(var + 1e-5f);
    float4 gv = ((const float4*)g)[tid];
    float4 bv = ((const float4*)b)[tid];
    float4 o;
    o.x = (v.x - mean) * rstd * gv.x + bv.x;
    o.y = (v.y - mean) * rstd * gv.y + bv.y;
    o.z = (v.z - mean) * rstd * gv.z + bv.z;
    o.w = (v.w - mean) * rstd * gv.w + bv.w;
    ((float4*)(out + (size_t)row * CD))[tid] = o;
}

// ---------------- SGEMM 128x128x8, 256 threads, 8x8 microtile --------------
// C[M,N] = A[M,K] @ B[K,N] (+bias[N]) (+res[M,N]) (optional relu)
// Requires M%128==0, N%128==0, K%8==0.
template <bool HAS_BIAS, bool HAS_RES, bool RELU>
__global__ __launch_bounds__(256)
void sgemm_kernel(const float* __restrict__ A, const float* __restrict__ B,
                  float* __restrict__ C, const float* __restrict__ bias,
                  const float* __restrict__ res, int M, int N, int K) {
    __shared__ float As[8][128];
    __shared__ float Bs[8][128];
    const int tid = threadIdx.x;
    const int bm = blockIdx.y * 128;
    const int bn = blockIdx.x * 128;

    const int a_row = tid >> 1;         // 0..127
    const int a_col = (tid & 1) * 4;    // 0 or 4
    const int b_row = tid >> 5;         // 0..7
    const int b_col = (tid & 31) * 4;   // 0..124

    const int tx = tid & 15;            // 0..15 -> n
    const int ty = tid >> 4;            // 0..15 -> m

    float acc[8][8];
    #pragma unroll
    for (int i = 0; i < 8; i++)
        #pragma unroll
        for (int j = 0; j < 8; j++) acc[i][j] = 0.f;

    for (int k0 = 0; k0 < K; k0 += 8) {
        float4 av = *(const float4*)&A[(size_t)(bm + a_row) * K + k0 + a_col];
        As[a_col + 0][a_row] = av.x;
        As[a_col + 1][a_row] = av.y;
        As[a_col + 2][a_row] = av.z;
        As[a_col + 3][a_row] = av.w;
        *(float4*)&Bs[b_row][b_col] =
            *(const float4*)&B[(size_t)(k0 + b_row) * N + bn + b_col];
        __syncthreads();
        #pragma unroll
        for (int kk = 0; kk < 8; kk++) {
            float4 a0 = *(const float4*)&As[kk][ty * 8];
            float4 a1 = *(const float4*)&As[kk][ty * 8 + 4];
            float4 b0 = *(const float4*)&Bs[kk][tx * 8];
            float4 b1 = *(const float4*)&Bs[kk][tx * 8 + 4];
            float a[8] = {a0.x, a0.y, a0.z, a0.w, a1.x, a1.y, a1.z, a1.w};
            float bb[8] = {b0.x, b0.y, b0.z, b0.w, b1.x, b1.y, b1.z, b1.w};
            #pragma unroll
            for (int i = 0; i < 8; i++)
                #pragma unroll
                for (int j = 0; j < 8; j++) acc[i][j] += a[i] * bb[j];
        }
        __syncthreads();
    }

    #pragma unroll
    for (int i = 0; i < 8; i++) {
        int m = bm + ty * 8 + i;
        #pragma unroll
        for (int j = 0; j < 8; j++) {
            int n = bn + tx * 8 + j;
            float v = acc[i][j];
            if (HAS_BIAS) v += bias[n];
            if (HAS_RES) v += res[(size_t)m * N + n];
            if (RELU) v = fmaxf(v, 0.f);
            C[(size_t)m * N + n] = v;
        }
    }
}

// ---------------- attention (one block per (b,h,t) row) --------------------
__global__ __launch_bounds__(128)
void attn_kernel(const float* __restrict__ qkv, float* __restrict__ out) {
    const int t = blockIdx.x;
    const int h = blockIdx.y;
    const int b = blockIdx.z;
    const int tid = threadIdx.x; // 128

    __shared__ float q_sh[CHS];
    __shared__ float sc[CT];
    __shared__ float red[4];

    const size_t rowq = ((size_t)(b * CT + t)) * (3 * CD) + h * CHS;
    if (tid < CHS) q_sh[tid] = qkv[rowq + tid];
    __syncthreads();

    const float scale = 0.03125f; // 1/sqrt(D), D=1024 (reference scales by d_model)

    // scores
    float lmax = -1e30f;
    for (int s = tid; s <= t; s += 128) {
        const float4* kp = (const float4*)(qkv + ((size_t)(b * CT + s)) * (3 * CD) + CD + h * CHS);
        float dot = 0.f;
        #pragma unroll
        for (int j = 0; j < 16; j++) {
            float4 kv = kp[j];
            dot += q_sh[4 * j + 0] * kv.x + q_sh[4 * j + 1] * kv.y +
                   q_sh[4 * j + 2] * kv.z + q_sh[4 * j + 3] * kv.w;
        }
        dot *= scale;
        sc[s] = dot;
        lmax = fmaxf(lmax, dot);
    }
    #pragma unroll
    for (int o = 16; o; o >>= 1) lmax = fmaxf(lmax, __shfl_xor_sync(0xffffffffu, lmax, o));
    int w = tid >> 5;
    if ((tid & 31) == 0) red[w] = lmax;
    __syncthreads();
    float bmax = fmaxf(fmaxf(red[0], red[1]), fmaxf(red[2], red[3]));
    __syncthreads(); // everyone has read red[] before it is reused

    float lsum = 0.f;
    for (int s = tid; s <= t; s += 128) {
        float p = expf(sc[s] - bmax);
        sc[s] = p;
        lsum += p;
    }
    lsum = warp_sum(lsum);
    if ((tid & 31) == 0) red[w] = lsum;
    __syncthreads(); // sc[] writes + red[] writes visible
    float inv = 1.f / (red[0] + red[1] + red[2] + red[3]);

    if (tid < CHS) {
        const float* vp = qkv + 2 * CD + h * CHS + tid;
        float acc = 0.f;
        #pragma unroll 4
        for (int s = 0; s <= t; s++)
            acc += sc[s] * vp[(size_t)(b * CT + s) * (3 * CD)];
        out[((size_t)(b * CT + t)) * CD + h * CHS + tid] = acc * inv;
    }
}

// ---------------- host orchestration --------------------------------------
extern "C" void kernel_launch(void* const* d_in, const int* in_sizes, int n_in,
                              void* d_out, int out_size) {
    const int*   token_ids = (const int*)d_in[0];
    const float* tok_emb   = (const float*)d_in[1];
    const float* pos_emb   = (const float*)d_in[2];
    const float* wq        = (const float*)d_in[3];
    const float* wk        = (const float*)d_in[4];
    const float* wv        = (const float*)d_in[5];
    const float* w_proj    = (const float*)d_in[6];
    const float* b_proj    = (const float*)d_in[7];
    const float* ln1_g     = (const float*)d_in[8];
    const float* ln1_b     = (const float*)d_in[9];
    const float* ln2_g     = (const float*)d_in[10];
    const float* ln2_b     = (const float*)d_in[11];
    const float* w1        = (const float*)d_in[12];
    const float* b1        = (const float*)d_in[13];
    const float* w2        = (const float*)d_in[14];
    const float* b2        = (const float*)d_in[15];
    const float* lnf_g     = (const float*)d_in[16];
    const float* lnf_b     = (const float*)d_in[17];
    const float* w_out     = (const float*)d_in[18];
    const float* b_out     = (const float*)d_in[19];
    float* out = (float*)d_out;

    float *x, *hbuf, *qkv, *act, *wpack;
    cudaGetSymbolAddress((void**)&x, g_x);
    cudaGetSymbolAddress((void**)&hbuf, g_h);
    cudaGetSymbolAddress((void**)&qkv, g_qkv);
    cudaGetSymbolAddress((void**)&act, g_act);
    cudaGetSymbolAddress((void**)&wpack, g_wpack);

    // 1) embedding
    {
        int n = CM * CD;
        embed_kernel<<<(n + 255) / 256, 256>>>(token_ids, tok_emb, pos_emb, x);
    }
    // 2) pack qkv weights for all layers
    {
        int n = 3 * CL * CH * CD * CHS;
        pack_qkv_kernel<<<(n + 255) / 256, 256>>>(wq, wk, wv, wpack);
    }

    dim3 attn_grid(CT, CH, CB);

    for (int l = 0; l < CL; l++) {
        // ln1 -> h
        ln_kernel<<<CM, 256>>>(x, ln1_g + l * CD, ln1_b + l * CD, hbuf);
        // qkv = h @ wpack[l]   (4096 x 3072 x 1024)
        {
            dim3 grid(3 * CD / 128, CM / 128);
            sgemm_kernel<false, false, false><<<grid, 256>>>(
                hbuf, wpack + (size_t)l * CD * 3 * CD, qkv, nullptr, nullptr,
                CM, 3 * CD, CD);
        }
        // attention -> h (concat heads layout (B,T,H*HS))
        attn_kernel<<<attn_grid, 128>>>(qkv, hbuf);
        // x = x + h @ w_proj[l] + b_proj[l]
        {
            dim3 grid(CD / 128, CM / 128);
            sgemm_kernel<true, true, false><<<grid, 256>>>(
                hbuf, w_proj + (size_t)l * CD * CD, x, b_proj + l * CD, x,
                CM, CD, CD);
        }
        // ln2 -> h
        ln_kernel<<<CM, 256>>>(x, ln2_g + l * CD, ln2_b + l * CD, hbuf);
        // act = relu(h @ w1[l] + b1[l])   (4096 x 4096 x 1024)
        {
            dim3 grid(CFF / 128, CM / 128);
            sgemm_kernel<true, false, true><<<grid, 256>>>(
                hbuf, w1 + (size_t)l * CD * CFF, act, b1 + (size_t)l * CFF, nullptr,
                CM, CFF, CD);
        }
        // x = x + act @ w2[l] + b2[l]   (4096 x 1024 x 4096)
        {
            dim3 grid(CD / 128, CM / 128);
            sgemm_kernel<true, true, false><<<grid, 256>>>(
                act, w2 + (size_t)l * CFF * CD, x, b2 + l * CD, x,
                CM, CD, CFF);
        }
    }

    // final ln -> h
    ln_kernel<<<CM, 256>>>(x, lnf_g, lnf_b, hbuf);
    // logits = h @ w_out + b_out   (4096 x 32000 x 1024)
    {
        dim3 grid(CV / 128, CM / 128);
        sgemm_kernel<true, false, false><<<grid, 256>>>(
            hbuf, w_out, out, b_out, nullptr, CM, CV, CD);
    }
}

// round 2
// speedup vs baseline: 2.8046x; 2.8046x over previous
#include <cuda_runtime.h>
#include <cstdint>
#include <cstdio>

// Problem constants
static constexpr int CB = 4;        // batch
static constexpr int CT = 1024;     // seq len
static constexpr int CD = 1024;     // d_model
static constexpr int CH = 16;       // heads
static constexpr int CHS = 64;      // head size
static constexpr int CL = 4;        // layers
static constexpr int CFF = 4096;    // ffn dim
static constexpr int CV = 32000;    // vocab
static constexpr int CM = CB * CT;  // 4096 rows

// ---------------- scratch (device globals; no allocation allowed) ----------
__device__ float g_x[CM * CD];          // residual stream (16 MB)
__device__ float g_h[CM * CD];          // ln output / attn-out (16 MB)
__device__ float g_qkv[CM * 3 * CD];    // packed qkv activations (50 MB)
__device__ float g_act[CM * CFF];       // ffn activation (67 MB)
__device__ float g_wpack[CL * CD * 3 * CD]; // packed qkv weights (50 MB)

// ---------------- embedding -----------------------------------------------
__global__ void embed_kernel(const int* __restrict__ ids,
                             const float* __restrict__ tok_emb,
                             const float* __restrict__ pos_emb,
                             float* __restrict__ x) {
    int idx = blockIdx.x * blockDim.x + threadIdx.x;
    if (idx >= CM * CD) return;
    int d = idx % CD;
    int bt = idx / CD;
    int t = bt % CT;
    x[idx] = tok_emb[(size_t)ids[bt] * CD + d] + pos_emb[t * CD + d];
}

// ---------------- qkv weight pack: (L,H,D,HS)x3 -> (L, D, 3*H*HS) ----------
__global__ void pack_qkv_kernel(const float* __restrict__ wq,
                                const float* __restrict__ wk,
                                const float* __restrict__ wv,
                                float* __restrict__ wp) {
    const int PER = CL * CH * CD * CHS; // 4194304
    int idx = blockIdx.x * blockDim.x + threadIdx.x;
    if (idx >= 3 * PER) return;
    int which = idx / PER;
    int r = idx % PER;
    int e = r % CHS;
    int d = (r / CHS) % CD;
    int h = (r / (CHS * CD)) % CH;
    int l = r / (CHS * CD * CH);
    const float* src = (which == 0) ? wq : (which == 1) ? wk : wv;
    wp[((size_t)l * CD + d) * (3 * CD) + which * CD + h * CHS + e] = src[r];
}

// ---------------- layernorm ------------------------------------------------
__device__ __forceinline__ float warp_sum(float v) {
    #pragma unroll
    for (int o = 16; o; o >>= 1) v += __shfl_xor_sync(0xffffffffu, v, o);
    return v;
}

__global__ void ln_kernel(const float* __restrict__ x,
                          const float* __restrict__ g,
                          const float* __restrict__ b,
                          float* __restrict__ out) {
    int row = blockIdx.x;
    int tid = threadIdx.x; // 256, each handles 4 elems
    const float4* xr = (const float4*)(x + (size_t)row * CD);
    float4 v = xr[tid];
    float s = v.x + v.y + v.z + v.w;
    float s2 = v.x * v.x + v.y * v.y + v.z * v.z + v.w * v.w;
    s = warp_sum(s);
    s2 = warp_sum(s2);
    __shared__ float shs[8], shs2[8];
    int w = tid >> 5, lane = tid & 31;
    if (lane == 0) { shs[w] = s; shs2[w] = s2; }
    __syncthreads();
    if (tid == 0) {
        float a = 0.f, a2 = 0.f;
        #pragma unroll
        for (int i = 0; i < 8; i++) { a += shs[i]; a2 += shs2[i]; }
        shs[0] = a; shs2[0] = a2;
    }
    __syncthreads();
    float mean = shs[0] * (1.f / CD);
    float var = shs2[0] * (1.f / CD) - mean * mean;
    float rstd = rsqrtf(var + 1e-5f);
    float4 gv = ((const float4*)g)[tid];
    float4 bv = ((const float4*)b)[tid];
    float4 o;
    o.x = (v.x - mean) * rstd * gv.x + bv.x;
    o.y = (v.y - mean) * rstd * gv.y + bv.y;
    o.z = (v.z - mean) * rstd * gv.z + bv.z;
    o.w = (v.w - mean) * rstd * gv.w + bv.w;
    ((float4*)(out + (size_t)row * CD))[tid] = o;
}

// ---------------- TF32 tensor-core GEMM ------------------------------------
// C[M,N] = A[M,K] @ B[K,N] (+bias[N]) (+res[M,N]) (optional relu)
// Block tile 128x128, K-stage 16 (double buffered), 8 warps (2M x 4N),
// warp tile 64x32 via mma.m16n8k8 tf32 (4x4 mma tiles).
// Requires M%128==0, N%128==0, K%16==0.

__device__ __forceinline__ uint32_t f2tf32(float f) {
    uint32_t u;
    asm("cvt.rna.tf32.f32 %0, %1;" : "=r"(u) : "f"(f));
    return u;
}

__device__ __forceinline__ void mma_tf32(float* c, const uint32_t* a, const uint32_t* b) {
    asm volatile(
        "mma.sync.aligned.m16n8k8.row.col.f32.tf32.tf32.f32 "
        "{%0,%1,%2,%3}, {%4,%5,%6,%7}, {%8,%9}, {%0,%1,%2,%3};"
        : "+f"(c[0]), "+f"(c[1]), "+f"(c[2]), "+f"(c[3])
        : "r"(a[0]), "r"(a[1]), "r"(a[2]), "r"(a[3]), "r"(b[0]), "r"(b[1]));
}

template <bool HAS_BIAS, bool HAS_RES, bool RELU>
__global__ __launch_bounds__(256, 2)
void tf32_gemm(const float* __restrict__ A, const float* __restrict__ B,
               float* __restrict__ C, const float* __restrict__ bias,
               const float* __restrict__ res, int M, int N, int K) {
    __shared__ uint32_t As[2][16][132];  // [k][m], padded
    __shared__ uint32_t Bs[2][16][132];  // [k][n], padded

    const int tid = threadIdx.x;
    const int lane = tid & 31;
    const int warp = tid >> 5;
    const int wm = warp & 1;   // 0..1 -> 64 rows
    const int wn = warp >> 1;  // 0..3 -> 32 cols
    const int bm = blockIdx.y * 128;
    const int bn = blockIdx.x * 128;

    const int g = lane >> 2;   // 0..7
    const int tg = lane & 3;   // 0..3

    // global load coords
    const int arow = tid >> 2;          // 0..63
    const int acol = (tid & 3) * 4;     // 0,4,8,12
    const int brow = tid >> 5;          // 0..7
    const int bcol = (tid & 31) * 4;    // 0..124

    float acc[4][4][4];
    #pragma unroll
    for (int i = 0; i < 4; i++)
        #pragma unroll
        for (int j = 0; j < 4; j++)
            #pragma unroll
            for (int k = 0; k < 4; k++) acc[i][j][k] = 0.f;

    float4 avr0, avr1, bvr0, bvr1;

    // prologue: load stage 0
    avr0 = *(const float4*)&A[(size_t)(bm + arow) * K + acol];
    avr1 = *(const float4*)&A[(size_t)(bm + arow + 64) * K + acol];
    bvr0 = *(const float4*)&B[(size_t)brow * N + bn + bcol];
    bvr1 = *(const float4*)&B[(size_t)(brow + 8) * N + bn + bcol];

    {
        As[0][acol + 0][arow] = f2tf32(avr0.x);
        As[0][acol + 1][arow] = f2tf32(avr0.y);
        As[0][acol + 2][arow] = f2tf32(avr0.z);
        As[0][acol + 3][arow] = f2tf32(avr0.w);
        As[0][acol + 0][arow + 64] = f2tf32(avr1.x);
        As[0][acol + 1][arow + 64] = f2tf32(avr1.y);
        As[0][acol + 2][arow + 64] = f2tf32(avr1.z);
        As[0][acol + 3][arow + 64] = f2tf32(avr1.w);
        uint4 t0 = make_uint4(f2tf32(bvr0.x), f2tf32(bvr0.y), f2tf32(bvr0.z), f2tf32(bvr0.w));
        uint4 t1 = make_uint4(f2tf32(bvr1.x), f2tf32(bvr1.y), f2tf32(bvr1.z), f2tf32(bvr1.w));
        *(uint4*)&Bs[0][brow][bcol] = t0;
        *(uint4*)&Bs[0][brow + 8][bcol] = t1;
    }
    __syncthreads();

    const int nstage = K >> 4;
    for (int s = 0; s < nstage; s++) {
        const int buf = s & 1;
        const bool more = (s + 1 < nstage);
        if (more) {
            const int k0 = (s + 1) << 4;
            avr0 = *(const float4*)&A[(size_t)(bm + arow) * K + k0 + acol];
            avr1 = *(const float4*)&A[(size_t)(bm + arow + 64) * K + k0 + acol];
            bvr0 = *(const float4*)&B[(size_t)(k0 + brow) * N + bn + bcol];
            bvr1 = *(const float4*)&B[(size_t)(k0 + brow + 8) * N + bn + bcol];
        }

        #pragma unroll
        for (int kk = 0; kk < 16; kk += 8) {
            uint32_t af[4][4], bf[4][2];
            #pragma unroll
            for (int mi = 0; mi < 4; mi++) {
                const int r0 = wm * 64 + mi * 16 + g;
                af[mi][0] = As[buf][kk + tg][r0];
                af[mi][1] = As[buf][kk + tg][r0 + 8];
                af[mi][2] = As[buf][kk + 4 + tg][r0];
                af[mi][3] = As[buf][kk + 4 + tg][r0 + 8];
            }
            #pragma unroll
            for (int ni = 0; ni < 4; ni++) {
                const int c0 = wn * 32 + ni * 8 + g;
                bf[ni][0] = Bs[buf][kk + tg][c0];
                bf[ni][1] = Bs[buf][kk + 4 + tg][c0];
            }
            #pragma unroll
            for (int mi = 0; mi < 4; mi++)
                #pragma unroll
                for (int ni = 0; ni < 4; ni++)
                    mma_tf32(acc[mi][ni], af[mi], bf[ni]);
        }

        if (more) {
            const int nb = buf ^ 1;
            As[nb][acol + 0][arow] = f2tf32(avr0.x);
            As[nb][acol + 1][arow] = f2tf32(avr0.y);
            As[nb][acol + 2][arow] = f2tf32(avr0.z);
            As[nb][acol + 3][arow] = f2tf32(avr0.w);
            As[nb][acol + 0][arow + 64] = f2tf32(avr1.x);
            As[nb][acol + 1][arow + 64] = f2tf32(avr1.y);
            As[nb][acol + 2][arow + 64] = f2tf32(avr1.z);
            As[nb][acol + 3][arow + 64] = f2tf32(avr1.w);
            uint4 t0 = make_uint4(f2tf32(bvr0.x), f2tf32(bvr0.y), f2tf32(bvr0.z), f2tf32(bvr0.w));
            uint4 t1 = make_uint4(f2tf32(bvr1.x), f2tf32(bvr1.y), f2tf32(bvr1.z), f2tf32(bvr1.w));
            *(uint4*)&Bs[nb][brow][bcol] = t0;
            *(uint4*)&Bs[nb][brow + 8][bcol] = t1;
        }
        __syncthreads();
    }

    // epilogue
    #pragma unroll
    for (int mi = 0; mi < 4; mi++) {
        #pragma unroll
        for (int ni = 0; ni < 4; ni++) {
            const int col = bn + wn * 32 + ni * 8 + 2 * tg;
            #pragma unroll
            for (int half = 0; half < 2; half++) {
                const int row = bm + wm * 64 + mi * 16 + g + half * 8;
                float2 v;
                v.x = acc[mi][ni][half * 2 + 0];
                v.y = acc[mi][ni][half * 2 + 1];
                if (HAS_BIAS) { v.x += bias[col]; v.y += bias[col + 1]; }
                if (HAS_RES) {
                    const float2 r = *(const float2*)&res[(size_t)row * N + col];
                    v.x += r.x; v.y += r.y;
                }
                if (RELU) { v.x = fmaxf(v.x, 0.f); v.y = fmaxf(v.y, 0.f); }
                *(float2*)&C[(size_t)row * N + col] = v;
            }
        }
    }
}

// ---------------- attention (one block per (b,h,t) row) --------------------
__global__ __launch_bounds__(128)
void attn_kernel(const float* __restrict__ qkv, float* __restrict__ out) {
    const int t = blockIdx.x;
    const int h = blockIdx.y;
    const int b = blockIdx.z;
    const int tid = threadIdx.x; // 128

    __shared__ float q_sh[CHS];
    __shared__ float sc[CT];
    __shared__ float red[4];
    __shared__ float pacc[2][CHS];

    const size_t rowq = ((size_t)(b * CT + t)) * (3 * CD) + h * CHS;
    if (tid < CHS) q_sh[tid] = qkv[rowq + tid];
    __syncthreads();

    const float scale = 0.03125f; // 1/sqrt(D), D=1024 (reference scales by d_model)

    // scores
    float lmax = -1e30f;
    for (int s = tid; s <= t; s += 128) {
        const float4* kp = (const float4*)(qkv + ((size_t)(b * CT + s)) * (3 * CD) + CD + h * CHS);
        float dot = 0.f;
        #pragma unroll
        for (int j = 0; j < 16; j++) {
            float4 kv = kp[j];
            dot += q_sh[4 * j + 0] * kv.x + q_sh[4 * j + 1] * kv.y +
                   q_sh[4 * j + 2] * kv.z + q_sh[4 * j + 3] * kv.w;
        }
        dot *= scale;
        sc[s] = dot;
        lmax = fmaxf(lmax, dot);
    }
    #pragma unroll
    for (int o = 16; o; o >>= 1) lmax = fmaxf(lmax, __shfl_xor_sync(0xffffffffu, lmax, o));
    int w = tid >> 5;
    if ((tid & 31) == 0) red[w] = lmax;
    __syncthreads();
    float bmax = fmaxf(fmaxf(red[0], red[1]), fmaxf(red[2], red[3]));
    __syncthreads(); // everyone has read red[] before it is reused

    float lsum = 0.f;
    for (int s = tid; s <= t; s += 128) {
        float p = expf(sc[s] - bmax);
        sc[s] = p;
        lsum += p;
    }
    lsum = warp_sum(lsum);
    if ((tid & 31) == 0) red[w] = lsum;
    __syncthreads(); // sc[] writes + red[] writes visible
    float inv = 1.f / (red[0] + red[1] + red[2] + red[3]);

    // PV: 128 threads, 2 s-groups of 64
    {
        const int e = tid & 63;
        const int grp = tid >> 6;
        const float* vp = qkv + 2 * CD + h * CHS + e;
        float acc = 0.f;
        for (int s = grp; s <= t; s += 2)
            acc += sc[s] * vp[(size_t)(b * CT + s) * (3 * CD)];
        pacc[grp][e] = acc;
    }
    __syncthreads();
    if (tid < CHS) {
        out[((size_t)(b * CT + t)) * CD + h * CHS + tid] =
            (pacc[0][tid] + pacc[1][tid]) * inv;
    }
}

// ---------------- host orchestration --------------------------------------
extern "C" void kernel_launch(void* const* d_in, const int* in_sizes, int n_in,
                              void* d_out, int out_size) {
    const int*   token_ids = (const int*)d_in[0];
    const float* tok_emb   = (const float*)d_in[1];
    const float* pos_emb   = (const float*)d_in[2];
    const float* wq        = (const float*)d_in[3];
    const float* wk        = (const float*)d_in[4];
    const float* wv        = (const float*)d_in[5];
    const float* w_proj    = (const float*)d_in[6];
    const float* b_proj    = (const float*)d_in[7];
    const float* ln1_g     = (const float*)d_in[8];
    const float* ln1_b     = (const float*)d_in[9];
    const float* ln2_g     = (const float*)d_in[10];
    const float* ln2_b     = (const float*)d_in[11];
    const float* w1        = (const float*)d_in[12];
    const float* b1        = (const float*)d_in[13];
    const float* w2        = (const float*)d_in[14];
    const float* b2        = (const float*)d_in[15];
    const float* lnf_g     = (const float*)d_in[16];
    const float* lnf_b     = (const float*)d_in[17];
    const float* w_out     = (const float*)d_in[18];
    const float* b_out     = (const float*)d_in[19];
    float* out = (float*)d_out;

    float *x, *hbuf, *qkv, *act, *wpack;
    cudaGetSymbolAddress((void**)&x, g_x);
    cudaGetSymbolAddress((void**)&hbuf, g_h);
    cudaGetSymbolAddress((void**)&qkv, g_qkv);
    cudaGetSymbolAddress((void**)&act, g_act);
    cudaGetSymbolAddress((void**)&wpack, g_wpack);

    // 1) embedding
    {
        int n = CM * CD;
        embed_kernel<<<(n + 255) / 256, 256>>>(token_ids, tok_emb, pos_emb, x);
    }
    // 2) pack qkv weights for all layers
    {
        int n = 3 * CL * CH * CD * CHS;
        pack_qkv_kernel<<<(n + 255) / 256, 256>>>(wq, wk, wv, wpack);
    }

    dim3 attn_grid(CT, CH, CB);

    for (int l = 0; l < CL; l++) {
        // ln1 -> h
        ln_kernel<<<CM, 256>>>(x, ln1_g + l * CD, ln1_b + l * CD, hbuf);
        // qkv = h @ wpack[l]   (4096 x 3072 x 1024)
        {
            dim3 grid(3 * CD / 128, CM / 128);
            tf32_gemm<false, false, false><<<grid, 256>>>(
                hbuf, wpack + (size_t)l * CD * 3 * CD, qkv, nullptr, nullptr,
                CM, 3 * CD, CD);
        }
        // attention -> h (concat heads layout (B,T,H*HS))
        attn_kernel<<<attn_grid, 128>>>(qkv, hbuf);
        // x = x + h @ w_proj[l] + b_proj[l]
        {
            dim3 grid(CD / 128, CM / 128);
            tf32_gemm<true, true, false><<<grid, 256>>>(
                hbuf, w_proj + (size_t)l * CD * CD, x, b_proj + l * CD, x,
                CM, CD, CD);
        }
        // ln2 -> h
        ln_kernel<<<CM, 256>>>(x, ln2_g + l * CD, ln2_b + l * CD, hbuf);
        // act = relu(h @ w1[l] + b1[l])   (4096 x 4096 x 1024)
        {
            dim3 grid(CFF / 128, CM / 128);
            tf32_gemm<true, false, true><<<grid, 256>>>(
                hbuf, w1 + (size_t)l * CD * CFF, act, b1 + (size_t)l * CFF, nullptr,
                CM, CFF, CD);
        }
        // x = x + act @ w2[l] + b2[l]   (4096 x 1024 x 4096)
        {
            dim3 grid(CD / 128, CM / 128);
            tf32_gemm<true, true, false><<<grid, 256>>>(
                act, w2 + (size_t)l * CFF * CD, x, b2 + l * CD, x,
                CM, CD, CFF);
        }
    }

    // final ln -> h
    ln_kernel<<<CM, 256>>>(x, lnf_g, lnf_b, hbuf);
    // logits = h @ w_out + b_out   (4096 x 32000 x 1024)
    {
        dim3 grid(CV / 128, CM / 128);
        tf32_gemm<true, false, false><<<grid, 256>>>(
            hbuf, w_out, out, b_out, nullptr, CM, CV, CD);
    }
}

// round 3
// speedup vs baseline: 5.4492x; 1.9430x over previous
#include <cuda_runtime.h>
#include <cstdint>
#include <cstdio>

// Problem constants
static constexpr int CB = 4;        // batch
static constexpr int CT = 1024;     // seq len
static constexpr int CD = 1024;     // d_model
static constexpr int CH = 16;       // heads
static constexpr int CHS = 64;      // head size
static constexpr int CL = 4;        // layers
static constexpr int CFF = 4096;    // ffn dim
static constexpr int CV = 32000;    // vocab
static constexpr int CM = CB * CT;  // 4096 rows

// ---------------- scratch (device globals; no allocation allowed) ----------
__device__ float g_x[CM * CD];          // residual stream (16 MB)
__device__ float g_h[CM * CD];          // ln output / attn-out (16 MB)
__device__ float g_qkv[CM * 3 * CD];    // packed qkv activations (50 MB)
__device__ float g_act[CM * CFF];       // ffn activation (67 MB)
__device__ float g_wpack[CL * CD * 3 * CD]; // packed qkv weights (50 MB)

// ---------------- embedding -----------------------------------------------
__global__ void embed_kernel(const int* __restrict__ ids,
                             const float* __restrict__ tok_emb,
                             const float* __restrict__ pos_emb,
                             float* __restrict__ x) {
    int idx = blockIdx.x * blockDim.x + threadIdx.x;
    if (idx >= CM * CD) return;
    int d = idx % CD;
    int bt = idx / CD;
    int t = bt % CT;
    x[idx] = tok_emb[(size_t)ids[bt] * CD + d] + pos_emb[t * CD + d];
}

// ---------------- qkv weight pack: (L,H,D,HS)x3 -> (L, D, 3*H*HS) ----------
__global__ void pack_qkv_kernel(const float* __restrict__ wq,
                                const float* __restrict__ wk,
                                const float* __restrict__ wv,
                                float* __restrict__ wp) {
    const int PER = CL * CH * CD * CHS; // 4194304
    int idx = blockIdx.x * blockDim.x + threadIdx.x;
    if (idx >= 3 * PER) return;
    int which = idx / PER;
    int r = idx % PER;
    int e = r % CHS;
    int d = (r / CHS) % CD;
    int h = (r / (CHS * CD)) % CH;
    int l = r / (CHS * CD * CH);
    const float* src = (which == 0) ? wq : (which == 1) ? wk : wv;
    wp[((size_t)l * CD + d) * (3 * CD) + which * CD + h * CHS + e] = src[r];
}

// ---------------- layernorm ------------------------------------------------
__device__ __forceinline__ float warp_sum(float v) {
    #pragma unroll
    for (int o = 16; o; o >>= 1) v += __shfl_xor_sync(0xffffffffu, v, o);
    return v;
}

__global__ void ln_kernel(const float* __restrict__ x,
                          const float* __restrict__ g,
                          const float* __restrict__ b,
                          float* __restrict__ out) {
    int row = blockIdx.x;
    int tid = threadIdx.x; // 256, each handles 4 elems
    const float4* xr = (const float4*)(x + (size_t)row * CD);
    float4 v = xr[tid];
    float s = v.x + v.y + v.z + v.w;
    float s2 = v.x * v.x + v.y * v.y + v.z * v.z + v.w * v.w;
    s = warp_sum(s);
    s2 = warp_sum(s2);
    __shared__ float shs[8], shs2[8];
    int w = tid >> 5, lane = tid & 31;
    if (lane == 0) { shs[w] = s; shs2[w] = s2; }
    __syncthreads();
    if (tid == 0) {
        float a = 0.f, a2 = 0.f;
        #pragma unroll
        for (int i = 0; i < 8; i++) { a += shs[i]; a2 += shs2[i]; }
        shs[0] = a; shs2[0] = a2;
    }
    __syncthreads();
    float mean = shs[0] * (1.f / CD);
    float var = shs2[0] * (1.f / CD) - mean * mean;
    float rstd = rsqrtf(var + 1e-5f);
    float4 gv = ((const float4*)g)[tid];
    float4 bv = ((const float4*)b)[tid];
    float4 o;
    o.x = (v.x - mean) * rstd * gv.x + bv.x;
    o.y = (v.y - mean) * rstd * gv.y + bv.y;
    o.z = (v.z - mean) * rstd * gv.z + bv.z;
    o.w = (v.w - mean) * rstd * gv.w + bv.w;
    ((float4*)(out + (size_t)row * CD))[tid] = o;
}

// ---------------- TF32 tensor-core GEMM ------------------------------------
__device__ __forceinline__ uint32_t f2tf32(float f) {
    uint32_t u;
    asm("cvt.rna.tf32.f32 %0, %1;" : "=r"(u) : "f"(f));
    return u;
}

__device__ __forceinline__ void mma_tf32(float* c, const uint32_t* a, const uint32_t* b) {
    asm volatile(
        "mma.sync.aligned.m16n8k8.row.col.f32.tf32.tf32.f32 "
        "{%0,%1,%2,%3}, {%4,%5,%6,%7}, {%8,%9}, {%0,%1,%2,%3};"
        : "+f"(c[0]), "+f"(c[1]), "+f"(c[2]), "+f"(c[3])
        : "r"(a[0]), "r"(a[1]), "r"(a[2]), "r"(a[3]), "r"(b[0]), "r"(b[1]));
}

template <bool HAS_BIAS, bool HAS_RES, bool RELU>
__global__ __launch_bounds__(256, 2)
void tf32_gemm(const float* __restrict__ A, const float* __restrict__ B,
               float* __restrict__ C, const float* __restrict__ bias,
               const float* __restrict__ res, int M, int N, int K) {
    __shared__ uint32_t As[2][16][132];  // [k][m], padded
    __shared__ uint32_t Bs[2][16][132];  // [k][n], padded

    const int tid = threadIdx.x;
    const int lane = tid & 31;
    const int warp = tid >> 5;
    const int wm = warp & 1;   // 0..1 -> 64 rows
    const int wn = warp >> 1;  // 0..3 -> 32 cols
    const int bm = blockIdx.y * 128;
    const int bn = blockIdx.x * 128;

    const int g = lane >> 2;   // 0..7
    const int tg = lane & 3;   // 0..3

    const int arow = tid >> 2;          // 0..63
    const int acol = (tid & 3) * 4;     // 0,4,8,12
    const int brow = tid >> 5;          // 0..7
    const int bcol = (tid & 31) * 4;    // 0..124

    float acc[4][4][4];
    #pragma unroll
    for (int i = 0; i < 4; i++)
        #pragma unroll
        for (int j = 0; j < 4; j++)
            #pragma unroll
            for (int k = 0; k < 4; k++) acc[i][j][k] = 0.f;

    float4 avr0, avr1, bvr0, bvr1;

    avr0 = *(const float4*)&A[(size_t)(bm + arow) * K + acol];
    avr1 = *(const float4*)&A[(size_t)(bm + arow + 64) * K + acol];
    bvr0 = *(const float4*)&B[(size_t)brow * N + bn + bcol];
    bvr1 = *(const float4*)&B[(size_t)(brow + 8) * N + bn + bcol];

    {
        As[0][acol + 0][arow] = f2tf32(avr0.x);
        As[0][acol + 1][arow] = f2tf32(avr0.y);
        As[0][acol + 2][arow] = f2tf32(avr0.z);
        As[0][acol + 3][arow] = f2tf32(avr0.w);
        As[0][acol + 0][arow + 64] = f2tf32(avr1.x);
        As[0][acol + 1][arow + 64] = f2tf32(avr1.y);
        As[0][acol + 2][arow + 64] = f2tf32(avr1.z);
        As[0][acol + 3][arow + 64] = f2tf32(avr1.w);
        uint4 t0 = make_uint4(f2tf32(bvr0.x), f2tf32(bvr0.y), f2tf32(bvr0.z), f2tf32(bvr0.w));
        uint4 t1 = make_uint4(f2tf32(bvr1.x), f2tf32(bvr1.y), f2tf32(bvr1.z), f2tf32(bvr1.w));
        *(uint4*)&Bs[0][brow][bcol] = t0;
        *(uint4*)&Bs[0][brow + 8][bcol] = t1;
    }
    __syncthreads();

    const int nstage = K >> 4;
    for (int s = 0; s < nstage; s++) {
        const int buf = s & 1;
        const bool more = (s + 1 < nstage);
        if (more) {
            const int k0 = (s + 1) << 4;
            avr0 = *(const float4*)&A[(size_t)(bm + arow) * K + k0 + acol];
            avr1 = *(const float4*)&A[(size_t)(bm + arow + 64) * K + k0 + acol];
            bvr0 = *(const float4*)&B[(size_t)(k0 + brow) * N + bn + bcol];
            bvr1 = *(const float4*)&B[(size_t)(k0 + brow + 8) * N + bn + bcol];
        }

        #pragma unroll
        for (int kk = 0; kk < 16; kk += 8) {
            uint32_t af[4][4], bf[4][2];
            #pragma unroll
            for (int mi = 0; mi < 4; mi++) {
                const int r0 = wm * 64 + mi * 16 + g;
                af[mi][0] = As[buf][kk + tg][r0];
                af[mi][1] = As[buf][kk + tg][r0 + 8];
                af[mi][2] = As[buf][kk + 4 + tg][r0];
                af[mi][3] = As[buf][kk + 4 + tg][r0 + 8];
            }
            #pragma unroll
            for (int ni = 0; ni < 4; ni++) {
                const int c0 = wn * 32 + ni * 8 + g;
                bf[ni][0] = Bs[buf][kk + tg][c0];
                bf[ni][1] = Bs[buf][kk + 4 + tg][c0];
            }
            #pragma unroll
            for (int mi = 0; mi < 4; mi++)
                #pragma unroll
                for (int ni = 0; ni < 4; ni++)
                    mma_tf32(acc[mi][ni], af[mi], bf[ni]);
        }

        if (more) {
            const int nb = buf ^ 1;
            As[nb][acol + 0][arow] = f2tf32(avr0.x);
            As[nb][acol + 1][arow] = f2tf32(avr0.y);
            As[nb][acol + 2][arow] = f2tf32(avr0.z);
            As[nb][acol + 3][arow] = f2tf32(avr0.w);
            As[nb][acol + 0][arow + 64] = f2tf32(avr1.x);
            As[nb][acol + 1][arow + 64] = f2tf32(avr1.y);
            As[nb][acol + 2][arow + 64] = f2tf32(avr1.z);
            As[nb][acol + 3][arow + 64] = f2tf32(avr1.w);
            uint4 t0 = make_uint4(f2tf32(bvr0.x), f2tf32(bvr0.y), f2tf32(bvr0.z), f2tf32(bvr0.w));
            uint4 t1 = make_uint4(f2tf32(bvr1.x), f2tf32(bvr1.y), f2tf32(bvr1.z), f2tf32(bvr1.w));
            *(uint4*)&Bs[nb][brow][bcol] = t0;
            *(uint4*)&Bs[nb][brow + 8][bcol] = t1;
        }
        __syncthreads();
    }

    #pragma unroll
    for (int mi = 0; mi < 4; mi++) {
        #pragma unroll
        for (int ni = 0; ni < 4; ni++) {
            const int col = bn + wn * 32 + ni * 8 + 2 * tg;
            #pragma unroll
            for (int half = 0; half < 2; half++) {
                const int row = bm + wm * 64 + mi * 16 + g + half * 8;
                float2 v;
                v.x = acc[mi][ni][half * 2 + 0];
                v.y = acc[mi][ni][half * 2 + 1];
                if (HAS_BIAS) { v.x += bias[col]; v.y += bias[col + 1]; }
                if (HAS_RES) {
                    const float2 r = *(const float2*)&res[(size_t)row * N + col];
                    v.x += r.x; v.y += r.y;
                }
                if (RELU) { v.x = fmaxf(v.x, 0.f); v.y = fmaxf(v.y, 0.f); }
                *(float2*)&C[(size_t)row * N + col] = v;
            }
        }
    }
}

// ---------------- flash-style tiled attention ------------------------------
// Grid: (CT/64, CH, CB), 256 threads. Q-tile 64 rows, s-tiles of 64.
// smem: Qs[k][q] (transposed), KPs union (Ks[k][s] then Ps[q][s]), Vs[s][e].
// Online softmax state (m,l) replicated in registers across 16-thread row groups.
static constexpr int APAD = 68;
static constexpr int ATT_SMEM = 3 * 64 * APAD * (int)sizeof(float); // 52224 B

__global__ __launch_bounds__(256)
void attn_tile_kernel(const float* __restrict__ qkv, float* __restrict__ out) {
    extern __shared__ float sm[];
    float* Qs = sm;                    // [64][APAD]  (k-major: Qs[k][q])
    float* KPs = sm + 64 * APAD;       // [64][APAD]  Ks[k][s] / Ps[q][s]
    float* Vs = sm + 2 * 64 * APAD;    // [64][APAD]  Vs[s][e]

    const int qt = blockIdx.x;
    const int h = blockIdx.y;
    const int b = blockIdx.z;
    const int tid = threadIdx.x;
    const int ty = tid >> 4;   // 0..15 -> q rows r0 = 4*ty
    const int tx = tid & 15;   // 0..15 -> cols c0 = 4*tx
    const int r0 = ty * 4;
    const int c0 = tx * 4;

    const size_t qkv_base = (size_t)(b * CT) * (3 * CD) + h * CHS;

    // load Q tile transposed: Qs[k][r]
    for (int idx = tid; idx < 64 * 64; idx += 256) {
        int r = idx >> 6, k = idx & 63;
        Qs[k * APAD + r] = qkv[qkv_base + (size_t)(qt * 64 + r) * (3 * CD) + k];
    }

    const float scale = 0.03125f; // 1/sqrt(1024): reference scales by d_model

    float m_i[4], l_i[4];
    float acc[4][4];
    #pragma unroll
    for (int i = 0; i < 4; i++) {
        m_i[i] = -1e30f;
        l_i[i] = 0.f;
        #pragma unroll
        for (int j = 0; j < 4; j++) acc[i][j] = 0.f;
    }

    for (int st = 0; st <= qt; st++) {
        __syncthreads();  // prior-iteration reads of KPs/Vs complete
        // load K tile transposed (Ks[k][s]) and V tile (Vs[s][e])
        for (int idx = tid; idx < 64 * 64; idx += 256) {
            int r = idx >> 6, k = idx & 63;
            KPs[k * APAD + r] =
                qkv[qkv_base + (size_t)(st * 64 + r) * (3 * CD) + CD + k];
        }
        for (int idx = tid; idx < 64 * 64; idx += 256) {
            int s = idx >> 6, e = idx & 63;
            Vs[s * APAD + e] =
                qkv[qkv_base + (size_t)(st * 64 + s) * (3 * CD) + 2 * CD + e];
        }
        __syncthreads();

        // QK^T: sc[i][j] = Q[r0+i] . K[c0+j]
        float sc[4][4];
        #pragma unroll
        for (int i = 0; i < 4; i++)
            #pragma unroll
            for (int j = 0; j < 4; j++) sc[i][j] = 0.f;
        #pragma unroll 8
        for (int k = 0; k < 64; k++) {
            float4 qv = *(const float4*)&Qs[k * APAD + r0];
            float4 kv = *(const float4*)&KPs[k * APAD + c0];
            float qa[4] = {qv.x, qv.y, qv.z, qv.w};
            float ka[4] = {kv.x, kv.y, kv.z, kv.w};
            #pragma unroll
            for (int i = 0; i < 4; i++)
                #pragma unroll
                for (int j = 0; j < 4; j++) sc[i][j] += qa[i] * ka[j];
        }

        // scale + causal mask
        const int tbase = qt * 64 + r0;
        const int sbase = st * 64 + c0;
        #pragma unroll
        for (int i = 0; i < 4; i++)
            #pragma unroll
            for (int j = 0; j < 4; j++) {
                float v = sc[i][j] * scale;
                sc[i][j] = (sbase + j > tbase + i) ? -1e30f : v;
            }

        // row max across the 16-thread row group
        float rmax[4];
        #pragma unroll
        for (int i = 0; i < 4; i++) {
            rmax[i] = fmaxf(fmaxf(sc[i][0], sc[i][1]), fmaxf(sc[i][2], sc[i][3]));
        }
        #pragma unroll
        for (int off = 1; off < 16; off <<= 1) {
            #pragma unroll
            for (int i = 0; i < 4; i++)
                rmax[i] = fmaxf(rmax[i], __shfl_xor_sync(0xffffffffu, rmax[i], off));
        }

        float scl[4], rsum[4];
        #pragma unroll
        for (int i = 0; i < 4; i++) {
            float mnew = fmaxf(m_i[i], rmax[i]);
            scl[i] = __expf(m_i[i] - mnew);
            m_i[i] = mnew;
            float rs = 0.f;
            #pragma unroll
            for (int j = 0; j < 4; j++) {
                sc[i][j] = __expf(sc[i][j] - mnew);
                rs += sc[i][j];
            }
            rsum[i] = rs;
        }
        #pragma unroll
        for (int off = 1; off < 16; off <<= 1) {
            #pragma unroll
            for (int i = 0; i < 4; i++)
                rsum[i] += __shfl_xor_sync(0xffffffffu, rsum[i], off);
        }
        #pragma unroll
        for (int i = 0; i < 4; i++) {
            l_i[i] = l_i[i] * scl[i] + rsum[i];
            #pragma unroll
            for (int j = 0; j < 4; j++) acc[i][j] *= scl[i];
        }

        __syncthreads();  // all KPs (K) reads finished before storing P
        #pragma unroll
        for (int i = 0; i < 4; i++) {
            float4 pv = make_float4(sc[i][0], sc[i][1], sc[i][2], sc[i][3]);
            *(float4*)&KPs[(r0 + i) * APAD + c0] = pv;  // Ps[q][s]
        }
        __syncthreads();  // P visible to all

        // PV: acc[i][e] += sum_s P[r0+i][s] * V[s][c0+e]
        #pragma unroll 4
        for (int s4 = 0; s4 < 64; s4 += 4) {
            float4 p0 = *(const float4*)&KPs[(r0 + 0) * APAD + s4];
            float4 p1 = *(const float4*)&KPs[(r0 + 1) * APAD + s4];
            float4 p2 = *(const float4*)&KPs[(r0 + 2) * APAD + s4];
            float4 p3 = *(const float4*)&KPs[(r0 + 3) * APAD + s4];
            float4 v0 = *(const float4*)&Vs[(s4 + 0) * APAD + c0];
            float4 v1 = *(const float4*)&Vs[(s4 + 1) * APAD + c0];
            float4 v2 = *(const float4*)&Vs[(s4 + 2) * APAD + c0];
            float4 v3 = *(const float4*)&Vs[(s4 + 3) * APAD + c0];
            float pr[4][4] = {{p0.x, p0.y, p0.z, p0.w},
                              {p1.x, p1.y, p1.z, p1.w},
                              {p2.x, p2.y, p2.z, p2.w},
                              {p3.x, p3.y, p3.z, p3.w}};
            float vr[4][4] = {{v0.x, v0.y, v0.z, v0.w},
                              {v1.x, v1.y, v1.z, v1.w},
                              {v2.x, v2.y, v2.z, v2.w},
                              {v3.x, v3.y, v3.z, v3.w}};
            #pragma unroll
            for (int i = 0; i < 4; i++)
                #pragma unroll
                for (int u = 0; u < 4; u++)
                    #pragma unroll
                    for (int j = 0; j < 4; j++)
                        acc[i][j] += pr[i][u] * vr[u][j];
        }
    }

    // epilogue: out[(b, t, h*64 + e)] = acc / l
    #pragma unroll
    for (int i = 0; i < 4; i++) {
        const float inv = 1.f / l_i[i];
        float4 v = make_float4(acc[i][0] * inv, acc[i][1] * inv,
                               acc[i][2] * inv, acc[i][3] * inv);
        *(float4*)&out[(size_t)(b * CT + qt * 64 + r0 + i) * CD + h * CHS + c0] = v;
    }
}

// ---------------- host orchestration --------------------------------------
extern "C" void kernel_launch(void* const* d_in, const int* in_sizes, int n_in,
                              void* d_out, int out_size) {
    const int*   token_ids = (const int*)d_in[0];
    const float* tok_emb   = (const float*)d_in[1];
    const float* pos_emb   = (const float*)d_in[2];
    const float* wq        = (const float*)d_in[3];
    const float* wk        = (const float*)d_in[4];
    const float* wv        = (const float*)d_in[5];
    const float* w_proj    = (const float*)d_in[6];
    const float* b_proj    = (const float*)d_in[7];
    const float* ln1_g     = (const float*)d_in[8];
    const float* ln1_b     = (const float*)d_in[9];
    const float* ln2_g     = (const float*)d_in[10];
    const float* ln2_b     = (const float*)d_in[11];
    const float* w1        = (const float*)d_in[12];
    const float* b1        = (const float*)d_in[13];
    const float* w2        = (const float*)d_in[14];
    const float* b2        = (const float*)d_in[15];
    const float* lnf_g     = (const float*)d_in[16];
    const float* lnf_b     = (const float*)d_in[17];
    const float* w_out     = (const float*)d_in[18];
    const float* b_out     = (const float*)d_in[19];
    float* out = (float*)d_out;

    float *x, *hbuf, *qkv, *act, *wpack;
    cudaGetSymbolAddress((void**)&x, g_x);
    cudaGetSymbolAddress((void**)&hbuf, g_h);
    cudaGetSymbolAddress((void**)&qkv, g_qkv);
    cudaGetSymbolAddress((void**)&act, g_act);
    cudaGetSymbolAddress((void**)&wpack, g_wpack);

    cudaFuncSetAttribute(attn_tile_kernel,
                         cudaFuncAttributeMaxDynamicSharedMemorySize, ATT_SMEM);

    // 1) embedding
    {
        int n = CM * CD;
        embed_kernel<<<(n + 255) / 256, 256>>>(token_ids, tok_emb, pos_emb, x);
    }
    // 2) pack qkv weights for all layers
    {
        int n = 3 * CL * CH * CD * CHS;
        pack_qkv_kernel<<<(n + 255) / 256, 256>>>(wq, wk, wv, wpack);
    }

    dim3 attn_grid(CT / 64, CH, CB);

    for (int l = 0; l < CL; l++) {
        // ln1 -> h
        ln_kernel<<<CM, 256>>>(x, ln1_g + l * CD, ln1_b + l * CD, hbuf);
        // qkv = h @ wpack[l]   (4096 x 3072 x 1024)
        {
            dim3 grid(3 * CD / 128, CM / 128);
            tf32_gemm<false, false, false><<<grid, 256>>>(
                hbuf, wpack + (size_t)l * CD * 3 * CD, qkv, nullptr, nullptr,
                CM, 3 * CD, CD);
        }
        // attention -> h (concat heads layout (B,T,H*HS))
        attn_tile_kernel<<<attn_grid, 256, ATT_SMEM>>>(qkv, hbuf);
        // x = x + h @ w_proj[l] + b_proj[l]
        {
            dim3 grid(CD / 128, CM / 128);
            tf32_gemm<true, true, false><<<grid, 256>>>(
                hbuf, w_proj + (size_t)l * CD * CD, x, b_proj + l * CD, x,
                CM, CD, CD);
        }
        // ln2 -> h
        ln_kernel<<<CM, 256>>>(x, ln2_g + l * CD, ln2_b + l * CD, hbuf);
        // act = relu(h @ w1[l] + b1[l])   (4096 x 4096 x 1024)
        {
            dim3 grid(CFF / 128, CM / 128);
            tf32_gemm<true, false, true><<<grid, 256>>>(
                hbuf, w1 + (size_t)l * CD * CFF, act, b1 + (size_t)l * CFF, nullptr,
                CM, CFF, CD);
        }
        // x = x + act @ w2[l] + b2[l]   (4096 x 1024 x 4096)
        {
            dim3 grid(CD / 128, CM / 128);
            tf32_gemm<true, true, false><<<grid, 256>>>(
                act, w2 + (size_t)l * CFF * CD, x, b2 + l * CD, x,
                CM, CD, CFF);
        }
    }

    // final ln -> h
    ln_kernel<<<CM, 256>>>(x, lnf_g, lnf_b, hbuf);
    // logits = h @ w_out + b_out   (4096 x 32000 x 1024)
    {
        dim3 grid(CV / 128, CM / 128);
        tf32_gemm<true, false, false><<<grid, 256>>>(
            hbuf, w_out, out, b_out, nullptr, CM, CV, CD);
    }
}

// round 5
// speedup vs baseline: 8.0161x; 1.4711x over previous
#include <cuda_runtime.h>
#include <cstdint>
#include <cstdio>

// Problem constants
static constexpr int CB = 4;        // batch
static constexpr int CT = 1024;     // seq len
static constexpr int CD = 1024;     // d_model
static constexpr int CH = 16;       // heads
static constexpr int CHS = 64;      // head size
static constexpr int CL = 4;        // layers
static constexpr int CFF = 4096;    // ffn dim
static constexpr int CV = 32000;    // vocab
static constexpr int CM = CB * CT;  // 4096 rows

// ---------------- scratch (device globals; no allocation allowed) ----------
__device__ float g_x[CM * CD];              // residual stream (16 MB)
__device__ float g_h[CM * CD];              // ln output / attn-out (16 MB)
__device__ float g_qkv[CM * 3 * CD];        // packed qkv activations (50 MB)
__device__ float g_act[CM * CFF];           // ffn activation (67 MB)
__device__ float g_wpack[CL * CD * 3 * CD]; // packed+rounded qkv weights (50 MB)
__device__ float g_wproj_r[CL * CD * CD];   // rounded w_proj (16 MB)
__device__ float g_w1_r[CL * CD * CFF];     // rounded w1 (67 MB)
__device__ float g_w2_r[CL * CFF * CD];     // rounded w2 (67 MB)
__device__ float g_wout_r[CD * CV];         // rounded w_out (131 MB)

// ---------------- tf32 helpers ---------------------------------------------
__device__ __forceinline__ uint32_t f2tf32(float f) {
    uint32_t u;
    asm("cvt.rna.tf32.f32 %0, %1;" : "=r"(u) : "f"(f));
    return u;
}
__device__ __forceinline__ float roundtf(float f) {
    return __uint_as_float(f2tf32(f));
}

__device__ __forceinline__ void mma_tf32(float* c, const uint32_t* a, const uint32_t* b) {
    asm volatile(
        "mma.sync.aligned.m16n8k8.row.col.f32.tf32.tf32.f32 "
        "{%0,%1,%2,%3}, {%4,%5,%6,%7}, {%8,%9}, {%0,%1,%2,%3};"
        : "+f"(c[0]), "+f"(c[1]), "+f"(c[2]), "+f"(c[3])
        : "r"(a[0]), "r"(a[1]), "r"(a[2]), "r"(a[3]), "r"(b[0]), "r"(b[1]));
}

__device__ __forceinline__ void cp_async16(uint32_t dst_smem, const void* src) {
    asm volatile("cp.async.cg.shared.global [%0], [%1], 16;" ::
                 "r"(dst_smem), "l"(src));
}
__device__ __forceinline__ void cp_commit() {
    asm volatile("cp.async.commit_group;");
}
template <int N>
__device__ __forceinline__ void cp_wait() {
    asm volatile("cp.async.wait_group %0;" :: "n"(N));
}

// ---------------- embedding -----------------------------------------------
__global__ void embed_kernel(const int* __restrict__ ids,
                             const float* __restrict__ tok_emb,
                             const float* __restrict__ pos_emb,
                             float* __restrict__ x) {
    int idx = blockIdx.x * blockDim.x + threadIdx.x;
    if (idx >= CM * CD) return;
    int d = idx % CD;
    int bt = idx / CD;
    int t = bt % CT;
    x[idx] = tok_emb[(size_t)ids[bt] * CD + d] + pos_emb[t * CD + d];
}

// ---------------- qkv weight pack (+tf32 round) ----------------------------
__global__ void pack_qkv_kernel(const float* __restrict__ wq,
                                const float* __restrict__ wk,
                                const float* __restrict__ wv,
                                float* __restrict__ wp) {
    const int PER = CL * CH * CD * CHS; // 4194304
    int idx = blockIdx.x * blockDim.x + threadIdx.x;
    if (idx >= 3 * PER) return;
    int which = idx / PER;
    int r = idx % PER;
    int e = r % CHS;
    int d = (r / CHS) % CD;
    int h = (r / (CHS * CD)) % CH;
    int l = r / (CHS * CD * CH);
    const float* src = (which == 0) ? wq : (which == 1) ? wk : wv;
    wp[((size_t)l * CD + d) * (3 * CD) + which * CD + h * CHS + e] = roundtf(src[r]);
}

// ---------------- weight tf32-round copy -----------------------------------
__global__ void round_copy_kernel(const float* __restrict__ src,
                                  float* __restrict__ dst, int n) {
    int idx = blockIdx.x * blockDim.x + threadIdx.x;
    if (idx * 4 >= n) return;
    float4 v = ((const float4*)src)[idx];
    v.x = roundtf(v.x); v.y = roundtf(v.y);
    v.z = roundtf(v.z); v.w = roundtf(v.w);
    ((float4*)dst)[idx] = v;
}

// ---------------- layernorm (tf32-rounded output) --------------------------
__device__ __forceinline__ float warp_sum(float v) {
    #pragma unroll
    for (int o = 16; o; o >>= 1) v += __shfl_xor_sync(0xffffffffu, v, o);
    return v;
}

__global__ void ln_kernel(const float* __restrict__ x,
                          const float* __restrict__ g,
                          const float* __restrict__ b,
                          float* __restrict__ out) {
    int row = blockIdx.x;
    int tid = threadIdx.x; // 256, each handles 4 elems
    const float4* xr = (const float4*)(x + (size_t)row * CD);
    float4 v = xr[tid];
    float s = v.x + v.y + v.z + v.w;
    float s2 = v.x * v.x + v.y * v.y + v.z * v.z + v.w * v.w;
    s = warp_sum(s);
    s2 = warp_sum(s2);
    __shared__ float shs[8], shs2[8];
    int w = tid >> 5, lane = tid & 31;
    if (lane == 0) { shs[w] = s; shs2[w] = s2; }
    __syncthreads();
    if (tid == 0) {
        float a = 0.f, a2 = 0.f;
        #pragma unroll
        for (int i = 0; i < 8; i++) { a += shs[i]; a2 += shs2[i]; }
        shs[0] = a; shs2[0] = a2;
    }
    __syncthreads();
    float mean = shs[0] * (1.f / CD);
    float var = shs2[0] * (1.f / CD) - mean * mean;
    float rstd = rsqrtf(var + 1e-5f);
    float4 gv = ((const float4*)g)[tid];
    float4 bv = ((const float4*)b)[tid];
    float4 o;
    o.x = roundtf((v.x - mean) * rstd * gv.x + bv.x);
    o.y = roundtf((v.y - mean) * rstd * gv.y + bv.y);
    o.z = roundtf((v.z - mean) * rstd * gv.z + bv.z);
    o.w = roundtf((v.w - mean) * rstd * gv.w + bv.w);
    ((float4*)(out + (size_t)row * CD))[tid] = o;
}

// ---------------- TF32 tensor-core GEMM v2 (cp.async 3-stage) --------------
// C[M,N] = A[M,K] @ B[K,N] (+bias) (+res) (relu) (round-out)
// A and B must already be tf32-rounded (raw bits consumed).
// Block 128x128, BK=32, 3-stage cp.async pipeline, 8 warps (2Mx4N),
// warp tile 64x32, thread 4x4 mma tiles of m16n8k8.
static constexpr int GSTAGES = 3;
static constexpr int G_AP = 36;    // A row pad (floats)
static constexpr int G_BP = 136;   // B row pad (floats)
static constexpr int G_ASZ = 128 * G_AP;   // floats per A stage
static constexpr int G_BSZ = 32 * G_BP;    // floats per B stage
static constexpr int GEMM_SMEM = GSTAGES * (G_ASZ + G_BSZ) * (int)sizeof(float);

template <bool HAS_BIAS, bool HAS_RES, bool RELU, bool ROUND_OUT>
__global__ __launch_bounds__(256, 2)
void tf32_gemm(const float* __restrict__ A, const float* __restrict__ B,
               float* __restrict__ C, const float* __restrict__ bias,
               const float* __restrict__ res, int M, int N, int K) {
    extern __shared__ float sm[];
    float* As = sm;                         // [GSTAGES][128][G_AP]
    float* Bs = sm + GSTAGES * G_ASZ;       // [GSTAGES][32][G_BP]

    const int tid = threadIdx.x;
    const int lane = tid & 31;
    const int warp = tid >> 5;
    const int wm = warp & 1;   // 0..1 -> 64 rows
    const int wn = warp >> 1;  // 0..3 -> 32 cols
    const int bm = blockIdx.y * 128;
    const int bn = blockIdx.x * 128;

    const int g = lane >> 2;   // 0..7
    const int tg = lane & 3;   // 0..3

    const uint32_t as_base = (uint32_t)__cvta_generic_to_shared(As);
    const uint32_t bs_base = (uint32_t)__cvta_generic_to_shared(Bs);

    // loader coords (per-thread 4 chunks of A, 4 of B per stage)
    const int a_row[4] = {tid >> 3, (tid + 256) >> 3, (tid + 512) >> 3, (tid + 768) >> 3};
    const int a_col = (tid & 7) * 4;
    const int b_row[4] = {tid >> 5, (tid + 256) >> 5, (tid + 512) >> 5, (tid + 768) >> 5};
    const int b_col = (tid & 31) * 4;

    auto load_stage = [&](int s, int k0) {
        #pragma unroll
        for (int it = 0; it < 4; it++) {
            cp_async16(as_base + (uint32_t)(s * G_ASZ + a_row[it] * G_AP + a_col) * 4,
                       &A[(size_t)(bm + a_row[it]) * K + k0 + a_col]);
        }
        #pragma unroll
        for (int it = 0; it < 4; it++) {
            cp_async16(bs_base + (uint32_t)(s * G_BSZ + b_row[it] * G_BP + b_col) * 4,
                       &B[(size_t)(k0 + b_row[it]) * N + bn + b_col]);
        }
    };

    float acc[4][4][4];
    #pragma unroll
    for (int i = 0; i < 4; i++)
        #pragma unroll
        for (int j = 0; j < 4; j++)
            #pragma unroll
            for (int k = 0; k < 4; k++) acc[i][j][k] = 0.f;

    const int nk = K >> 5;
    // prologue: stages 0..GSTAGES-2
    #pragma unroll
    for (int s = 0; s < GSTAGES - 1; s++) {
        load_stage(s, s * 32);
        cp_commit();
    }
    cp_wait<GSTAGES - 2>();
    __syncthreads();

    for (int ks = 0; ks < nk; ks++) {
        const int buf = ks % GSTAGES;
        const int pre = ks + GSTAGES - 1;
        if (pre < nk) load_stage(pre % GSTAGES, pre * 32);
        cp_commit();

        const float* Ab = As + buf * G_ASZ;
        const float* Bb = Bs + buf * G_BSZ;
        #pragma unroll
        for (int kk = 0; kk < 32; kk += 8) {
            uint32_t af[4][4], bf[4][2];
            #pragma unroll
            for (int mi = 0; mi < 4; mi++) {
                const int r0 = wm * 64 + mi * 16 + g;
                af[mi][0] = __float_as_uint(Ab[r0 * G_AP + kk + tg]);
                af[mi][1] = __float_as_uint(Ab[(r0 + 8) * G_AP + kk + tg]);
                af[mi][2] = __float_as_uint(Ab[r0 * G_AP + kk + 4 + tg]);
                af[mi][3] = __float_as_uint(Ab[(r0 + 8) * G_AP + kk + 4 + tg]);
            }
            #pragma unroll
            for (int ni = 0; ni < 4; ni++) {
                const int c0 = wn * 32 + ni * 8 + g;
                bf[ni][0] = __float_as_uint(Bb[(kk + tg) * G_BP + c0]);
                bf[ni][1] = __float_as_uint(Bb[(kk + 4 + tg) * G_BP + c0]);
            }
            #pragma unroll
            for (int mi = 0; mi < 4; mi++)
                #pragma unroll
                for (int ni = 0; ni < 4; ni++)
                    mma_tf32(acc[mi][ni], af[mi], bf[ni]);
        }

        cp_wait<GSTAGES - 2>();
        __syncthreads();
    }

    // epilogue
    #pragma unroll
    for (int mi = 0; mi < 4; mi++) {
        #pragma unroll
        for (int ni = 0; ni < 4; ni++) {
            const int col = bn + wn * 32 + ni * 8 + 2 * tg;
            #pragma unroll
            for (int half = 0; half < 2; half++) {
                const int row = bm + wm * 64 + mi * 16 + g + half * 8;
                float2 v;
                v.x = acc[mi][ni][half * 2 + 0];
                v.y = acc[mi][ni][half * 2 + 1];
                if (HAS_BIAS) { v.x += bias[col]; v.y += bias[col + 1]; }
                if (HAS_RES) {
                    const float2 r = *(const float2*)&res[(size_t)row * N + col];
                    v.x += r.x; v.y += r.y;
                }
                if (RELU) { v.x = fmaxf(v.x, 0.f); v.y = fmaxf(v.y, 0.f); }
                if (ROUND_OUT) { v.x = roundtf(v.x); v.y = roundtf(v.y); }
                *(float2*)&C[(size_t)row * N + col] = v;
            }
        }
    }
}

// ---------------- flash-style tiled attention ------------------------------
static constexpr int APAD = 68;
static constexpr int ATT_SMEM = 3 * 64 * APAD * (int)sizeof(float); // 52224 B

__global__ __launch_bounds__(256)
void attn_tile_kernel(const float* __restrict__ qkv, float* __restrict__ out) {
    extern __shared__ float sm[];
    float* Qs = sm;                    // [64][APAD]  (k-major: Qs[k][q])
    float* KPs = sm + 64 * APAD;       // [64][APAD]  Ks[k][s] / Ps[q][s]
    float* Vs = sm + 2 * 64 * APAD;    // [64][APAD]  Vs[s][e]

    const int qt = blockIdx.x;
    const int h = blockIdx.y;
    const int b = blockIdx.z;
    const int tid = threadIdx.x;
    const int ty = tid >> 4;
    const int tx = tid & 15;
    const int r0 = ty * 4;
    const int c0 = tx * 4;

    const size_t qkv_base = (size_t)(b * CT) * (3 * CD) + h * CHS;

    for (int idx = tid; idx < 64 * 64; idx += 256) {
        int r = idx >> 6, k = idx & 63;
        Qs[k * APAD + r] = qkv[qkv_base + (size_t)(qt * 64 + r) * (3 * CD) + k];
    }

    const float scale = 0.03125f; // 1/sqrt(1024): reference scales by d_model

    float m_i[4], l_i[4];
    float acc[4][4];
    #pragma unroll
    for (int i = 0; i < 4; i++) {
        m_i[i] = -1e30f;
        l_i[i] = 0.f;
        #pragma unroll
        for (int j = 0; j < 4; j++) acc[i][j] = 0.f;
    }

    for (int st = 0; st <= qt; st++) {
        __syncthreads();
        for (int idx = tid; idx < 64 * 64; idx += 256) {
            int r = idx >> 6, k = idx & 63;
            KPs[k * APAD + r] =
                qkv[qkv_base + (size_t)(st * 64 + r) * (3 * CD) + CD + k];
        }
        for (int idx = tid; idx < 64 * 64; idx += 256) {
            int s = idx >> 6, e = idx & 63;
            Vs[s * APAD + e] =
                qkv[qkv_base + (size_t)(st * 64 + s) * (3 * CD) + 2 * CD + e];
        }
        __syncthreads();

        float sc[4][4];
        #pragma unroll
        for (int i = 0; i < 4; i++)
            #pragma unroll
            for (int j = 0; j < 4; j++) sc[i][j] = 0.f;
        #pragma unroll 8
        for (int k = 0; k < 64; k++) {
            float4 qv = *(const float4*)&Qs[k * APAD + r0];
            float4 kv = *(const float4*)&KPs[k * APAD + c0];
            float qa[4] = {qv.x, qv.y, qv.z, qv.w};
            float ka[4] = {kv.x, kv.y, kv.z, kv.w};
            #pragma unroll
            for (int i = 0; i < 4; i++)
                #pragma unroll
                for (int j = 0; j < 4; j++) sc[i][j] += qa[i] * ka[j];
        }

        const int tbase = qt * 64 + r0;
        const int sbase = st * 64 + c0;
        #pragma unroll
        for (int i = 0; i < 4; i++)
            #pragma unroll
            for (int j = 0; j < 4; j++) {
                float v = sc[i][j] * scale;
                sc[i][j] = (sbase + j > tbase + i) ? -1e30f : v;
            }

        float rmax[4];
        #pragma unroll
        for (int i = 0; i < 4; i++)
            rmax[i] = fmaxf(fmaxf(sc[i][0], sc[i][1]), fmaxf(sc[i][2], sc[i][3]));
        #pragma unroll
        for (int off = 1; off < 16; off <<= 1) {
            #pragma unroll
            for (int i = 0; i < 4; i++)
                rmax[i] = fmaxf(rmax[i], __shfl_xor_sync(0xffffffffu, rmax[i], off));
        }

        float scl[4], rsum[4];
        #pragma unroll
        for (int i = 0; i < 4; i++) {
            float mnew = fmaxf(m_i[i], rmax[i]);
            scl[i] = __expf(m_i[i] - mnew);
            m_i[i] = mnew;
            float rs = 0.f;
            #pragma unroll
            for (int j = 0; j < 4; j++) {
                sc[i][j] = __expf(sc[i][j] - mnew);
                rs += sc[i][j];
            }
            rsum[i] = rs;
        }
        #pragma unroll
        for (int off = 1; off < 16; off <<= 1) {
            #pragma unroll
            for (int i = 0; i < 4; i++)
                rsum[i] += __shfl_xor_sync(0xffffffffu, rsum[i], off);
        }
        #pragma unroll
        for (int i = 0; i < 4; i++) {
            l_i[i] = l_i[i] * scl[i] + rsum[i];
            #pragma unroll
            for (int j = 0; j < 4; j++) acc[i][j] *= scl[i];
        }

        __syncthreads();
        #pragma unroll
        for (int i = 0; i < 4; i++) {
            float4 pv = make_float4(sc[i][0], sc[i][1], sc[i][2], sc[i][3]);
            *(float4*)&KPs[(r0 + i) * APAD + c0] = pv;
        }
        __syncthreads();

        #pragma unroll 4
        for (int s4 = 0; s4 < 64; s4 += 4) {
            float4 p0 = *(const float4*)&KPs[(r0 + 0) * APAD + s4];
            float4 p1 = *(const float4*)&KPs[(r0 + 1) * APAD + s4];
            float4 p2 = *(const float4*)&KPs[(r0 + 2) * APAD + s4];
            float4 p3 = *(const float4*)&KPs[(r0 + 3) * APAD + s4];
            float4 v0 = *(const float4*)&Vs[(s4 + 0) * APAD + c0];
            float4 v1 = *(const float4*)&Vs[(s4 + 1) * APAD + c0];
            float4 v2 = *(const float4*)&Vs[(s4 + 2) * APAD + c0];
            float4 v3 = *(const float4*)&Vs[(s4 + 3) * APAD + c0];
            float pr[4][4] = {{p0.x, p0.y, p0.z, p0.w},
                              {p1.x, p1.y, p1.z, p1.w},
                              {p2.x, p2.y, p2.z, p2.w},
                              {p3.x, p3.y, p3.z, p3.w}};
            float vr[4][4] = {{v0.x, v0.y, v0.z, v0.w},
                              {v1.x, v1.y, v1.z, v1.w},
                              {v2.x, v2.y, v2.z, v2.w},
                              {v3.x, v3.y, v3.z, v3.w}};
            #pragma unroll
            for (int i = 0; i < 4; i++)
                #pragma unroll
                for (int u = 0; u < 4; u++)
                    #pragma unroll
                    for (int j = 0; j < 4; j++)
                        acc[i][j] += pr[i][u] * vr[u][j];
        }
    }

    // epilogue: out rounded to tf32 (consumed only by proj GEMM)
    #pragma unroll
    for (int i = 0; i < 4; i++) {
        const float inv = 1.f / l_i[i];
        float4 v = make_float4(roundtf(acc[i][0] * inv), roundtf(acc[i][1] * inv),
                               roundtf(acc[i][2] * inv), roundtf(acc[i][3] * inv));
        *(float4*)&out[(size_t)(b * CT + qt * 64 + r0 + i) * CD + h * CHS + c0] = v;
    }
}

// ---------------- host orchestration --------------------------------------
extern "C" void kernel_launch(void* const* d_in, const int* in_sizes, int n_in,
                              void* d_out, int out_size) {
    const int*   token_ids = (const int*)d_in[0];
    const float* tok_emb   = (const float*)d_in[1];
    const float* pos_emb   = (const float*)d_in[2];
    const float* wq        = (const float*)d_in[3];
    const float* wk        = (const float*)d_in[4];
    const float* wv        = (const float*)d_in[5];
    const float* w_proj    = (const float*)d_in[6];
    const float* b_proj    = (const float*)d_in[7];
    const float* ln1_g     = (const float*)d_in[8];
    const float* ln1_b     = (const float*)d_in[9];
    const float* ln2_g     = (const float*)d_in[10];
    const float* ln2_b     = (const float*)d_in[11];
    const float* w1        = (const float*)d_in[12];
    const float* b1        = (const float*)d_in[13];
    const float* w2        = (const float*)d_in[14];
    const float* b2        = (const float*)d_in[15];
    const float* lnf_g     = (const float*)d_in[16];
    const float* lnf_b     = (const float*)d_in[17];
    const float* w_out     = (const float*)d_in[18];
    const float* b_out     = (const float*)d_in[19];
    float* out = (float*)d_out;

    float *x, *hbuf, *qkv, *act, *wpack, *wproj_r, *w1_r, *w2_r, *wout_r;
    cudaGetSymbolAddress((void**)&x, g_x);
    cudaGetSymbolAddress((void**)&hbuf, g_h);
    cudaGetSymbolAddress((void**)&qkv, g_qkv);
    cudaGetSymbolAddress((void**)&act, g_act);
    cudaGetSymbolAddress((void**)&wpack, g_wpack);
    cudaGetSymbolAddress((void**)&wproj_r, g_wproj_r);
    cudaGetSymbolAddress((void**)&w1_r, g_w1_r);
    cudaGetSymbolAddress((void**)&w2_r, g_w2_r);
    cudaGetSymbolAddress((void**)&wout_r, g_wout_r);

    cudaFuncSetAttribute(attn_tile_kernel,
                         cudaFuncAttributeMaxDynamicSharedMemorySize, ATT_SMEM);
    cudaFuncSetAttribute(tf32_gemm<false, false, false, false>,
                         cudaFuncAttributeMaxDynamicSharedMemorySize, GEMM_SMEM);
    cudaFuncSetAttribute(tf32_gemm<true, true, false, false>,
                         cudaFuncAttributeMaxDynamicSharedMemorySize, GEMM_SMEM);
    cudaFuncSetAttribute(tf32_gemm<true, false, true, true>,
                         cudaFuncAttributeMaxDynamicSharedMemorySize, GEMM_SMEM);
    cudaFuncSetAttribute(tf32_gemm<true, false, false, false>,
                         cudaFuncAttributeMaxDynamicSharedMemorySize, GEMM_SMEM);

    // 1) embedding
    {
        int n = CM * CD;
        embed_kernel<<<(n + 255) / 256, 256>>>(token_ids, tok_emb, pos_emb, x);
    }
    // 2) pack+round qkv weights; round other weights
    {
        int n = 3 * CL * CH * CD * CHS;
        pack_qkv_kernel<<<(n + 255) / 256, 256>>>(wq, wk, wv, wpack);
    }
    {
        int n = CL * CD * CD;
        round_copy_kernel<<<(n / 4 + 255) / 256, 256>>>(w_proj, wproj_r, n);
        n = CL * CD * CFF;
        round_copy_kernel<<<(n / 4 + 255) / 256, 256>>>(w1, w1_r, n);
        n = CL * CFF * CD;
        round_copy_kernel<<<(n / 4 + 255) / 256, 256>>>(w2, w2_r, n);
        n = CD * CV;
        round_copy_kernel<<<(n / 4 + 255) / 256, 256>>>(w_out, wout_r, n);
    }

    dim3 attn_grid(CT / 64, CH, CB);

    for (int l = 0; l < CL; l++) {
        // ln1 -> h (tf32-rounded)
        ln_kernel<<<CM, 256>>>(x, ln1_g + l * CD, ln1_b + l * CD, hbuf);
        // qkv = h @ wpack[l]   (4096 x 3072 x 1024)
        {
            dim3 grid(3 * CD / 128, CM / 128);
            tf32_gemm<false, false, false, false><<<grid, 256, GEMM_SMEM>>>(
                hbuf, wpack + (size_t)l * CD * 3 * CD, qkv, nullptr, nullptr,
                CM, 3 * CD, CD);
        }
        // attention -> h (tf32-rounded output)
        attn_tile_kernel<<<attn_grid, 256, ATT_SMEM>>>(qkv, hbuf);
        // x = x + h @ w_proj[l] + b_proj[l]
        {
            dim3 grid(CD / 128, CM / 128);
            tf32_gemm<true, true, false, false><<<grid, 256, GEMM_SMEM>>>(
                hbuf, wproj_r + (size_t)l * CD * CD, x, b_proj + l * CD, x,
                CM, CD, CD);
        }
        // ln2 -> h (tf32-rounded)
        ln_kernel<<<CM, 256>>>(x, ln2_g + l * CD, ln2_b + l * CD, hbuf);
        // act = relu(h @ w1[l] + b1[l]) (rounded)
        {
            dim3 grid(CFF / 128, CM / 128);
            tf32_gemm<true, false, true, true><<<grid, 256, GEMM_SMEM>>>(
                hbuf, w1_r + (size_t)l * CD * CFF, act, b1 + (size_t)l * CFF, nullptr,
                CM, CFF, CD);
        }
        // x = x + act @ w2[l] + b2[l]
        {
            dim3 grid(CD / 128, CM / 128);
            tf32_gemm<true, true, false, false><<<grid, 256, GEMM_SMEM>>>(
                act, w2_r + (size_t)l * CFF * CD, x, b2 + l * CD, x,
                CM, CD, CFF);
        }
    }

    // final ln -> h (rounded)
    ln_kernel<<<CM, 256>>>(x, lnf_g, lnf_b, hbuf);
    // logits = h @ w_out + b_out   (4096 x 32000 x 1024)
    {
        dim3 grid(CV / 128, CM / 128);
        tf32_gemm<true, false, false, false><<<grid, 256, GEMM_SMEM>>>(
            hbuf, wout_r, out, b_out, nullptr, CM, CV, CD);
    }
}